// round 4
// baseline (speedup 1.0000x reference)
#include <cuda_runtime.h>

#define SEQ   1024
#define BATCH 512
#define NT    64
#define TPB   256          // 4 threads per tag

// Per-batch log-likelihoods (scratch; device global, no allocation).
__device__ float g_llh[BATCH];

__global__ void __launch_bounds__(TPB)
crf_forward_kernel(const float* __restrict__ em,
                   const void* __restrict__ tags_raw,
                   const int* __restrict__ mask,
                   const float* __restrict__ startT,
                   const float* __restrict__ endT,
                   const float* __restrict__ trans)
{
    const int b    = blockIdx.x;      // one batch element per block
    const int tid  = threadIdx.x;
    const int j    = tid >> 2;        // tag index 0..63
    const int p    = tid & 3;         // partial-dot slice 0..3
    const int lane = tid & 31;
    const int warp = tid >> 5;        // 0..7

    __shared__ float sh_e[2][NT];     // double-buffered beta (linear domain)
    __shared__ float sh_num[8];       // per-warp numerator partials
    __shared__ int   sh_len[8];       // per-warp length partials
    __shared__ float sh_sum[8];       // final sum partials

    // ---- tags dtype detection: int64 => every odd 32-bit word is 0 ----
    const int*       t32 = (const int*)tags_raw;
    const long long* t64 = (const long long*)tags_raw;
    bool is64 = true;
#pragma unroll
    for (int k = 0; k < 16; ++k)
        is64 = is64 && (t32[2 * k * 1031 + 1] == 0);

    // ---- exp(transitions): this thread's 16-row slice of column j ----
    float eT[16];
#pragma unroll
    for (int i = 0; i < 16; ++i)
        eT[i] = __expf(trans[(16 * p + i) * NT + j]);

    // ---- sequence length (mask monotone: mask[t] = t < length) ----
    int cnt = 0;
#pragma unroll
    for (int t = tid; t < SEQ; t += TPB)
        cnt += mask[t * BATCH + b];
#pragma unroll
    for (int o = 16; o > 0; o >>= 1)
        cnt += __shfl_xor_sync(0xffffffffu, cnt, o);
    if (lane == 0) sh_len[warp] = cnt;
    __syncthreads();
    int length = 0;
#pragma unroll
    for (int k = 0; k < 8; ++k) length += sh_len[k];

    // ---- numerator partials: t in [1, length) ----
    float num = 0.f;
    if (is64) {
        for (int t = 1 + tid; t < length; t += TPB) {
            const int pt = (int)t64[(t - 1) * BATCH + b];
            const int ct = (int)t64[t * BATCH + b];
            num += trans[pt * NT + ct] + em[(t * BATCH + b) * NT + ct];
        }
    } else {
        for (int t = 1 + tid; t < length; t += TPB) {
            const int pt = t32[(t - 1) * BATCH + b];
            const int ct = t32[t * BATCH + b];
            num += trans[pt * NT + ct] + em[(t * BATCH + b) * NT + ct];
        }
    }
#pragma unroll
    for (int o = 16; o > 0; o >>= 1)
        num += __shfl_xor_sync(0xffffffffu, num, o);
    if (lane == 0) sh_num[warp] = num;

    // ---- init beta_0 = exp(start + em_0) (p==0 threads own tag j) ----
    if (p == 0)
        sh_e[0][j] = __expf(startT[j] + em[b * NT + j]);

    // emission prefetch ring (p==0 threads only): emr[(s-1)&3] = em for step s
    float emr[4] = {0.f, 0.f, 0.f, 0.f};
    float expCur = 1.f;
    if (p == 0) {
#pragma unroll
        for (int d = 0; d < 4; ++d)
            emr[d] = (1 + d < length) ? em[((1 + d) * BATCH + b) * NT + j] : 0.f;
        expCur = __expf(emr[0]);      // exp(em) for step t=1
    }

    int ktot = 0;                      // power-of-2 renorm exponent (uniform)
    __syncthreads();

    for (int t = 1; t < length; ++t) {
        if (p == 0 && t + 4 < length)
            emr[(t + 3) & 3] = em[((t + 4) * BATCH + b) * NT + j];

        const int prev = (t - 1) & 1;
        const float* __restrict__ e = sh_e[prev];

        // renorm every 4 steps: exact power-of-2 scale from beta[0]
        float scale = 1.0f;
        if ((t & 3) == 0) {
            const int k = ((__float_as_int(e[0]) >> 23) & 0xFF) - 127;
            scale = __int_as_float((127 - k) << 23);   // 2^-k, exact
            ktot += k;
        }

        // 16-element partial dot: i in [16p, 16p+16)
        const float4* __restrict__ e4 = (const float4*)(e + 16 * p);
        const float4 a0 = e4[0], a1 = e4[1], a2 = e4[2], a3 = e4[3];
        float s0 = a0.x * eT[0], s1 = a0.y * eT[1];
        float s2 = a0.z * eT[2], s3 = a0.w * eT[3];
        s0 = fmaf(a1.x, eT[4], s0); s1 = fmaf(a1.y, eT[5], s1);
        s2 = fmaf(a1.z, eT[6], s2); s3 = fmaf(a1.w, eT[7], s3);
        s0 = fmaf(a2.x, eT[8], s0); s1 = fmaf(a2.y, eT[9], s1);
        s2 = fmaf(a2.z, eT[10], s2); s3 = fmaf(a2.w, eT[11], s3);
        s0 = fmaf(a3.x, eT[12], s0); s1 = fmaf(a3.y, eT[13], s1);
        s2 = fmaf(a3.z, eT[14], s2); s3 = fmaf(a3.w, eT[15], s3);
        float s = (s0 + s1) + (s2 + s3);

        // fold the 4 slices (p) within the warp
        s += __shfl_xor_sync(0xffffffffu, s, 1);
        s += __shfl_xor_sync(0xffffffffu, s, 2);

        if (p == 0) {
            sh_e[t & 1][j] = s * (expCur * scale);
            expCur = __expf(emr[t & 3]);   // exp(em) for step t+1
        }
        __syncthreads();
    }

    // ---- denominator: ktot*ln2 + log(sum_j beta_j * exp(end_j)) ----
    float v = 0.f;
    if (p == 0)
        v = sh_e[(length - 1) & 1][j] * __expf(endT[j]);
#pragma unroll
    for (int o = 16; o > 0; o >>= 1)
        v += __shfl_xor_sync(0xffffffffu, v, o);
    if (lane == 0) sh_sum[warp] = v;
    __syncthreads();

    if (tid == 0) {
        float sum = 0.f, numt = 0.f;
#pragma unroll
        for (int k = 0; k < 8; ++k) { sum += sh_sum[k]; numt += sh_num[k]; }
        const double denom = (double)ktot * 0.6931471805599453
                           + (double)logf(sum);
        const int t0 = is64 ? (int)t64[b] : t32[b];
        const int tl = is64 ? (int)t64[(length - 1) * BATCH + b]
                            : t32[(length - 1) * BATCH + b];
        const double numer = (double)numt
                           + (double)(startT[t0] + em[b * NT + t0] + endT[tl]);
        g_llh[b] = (float)(numer - denom);
    }
}

// Deterministic fixed-order tree reduction (double accumulation).
__global__ void __launch_bounds__(BATCH)
crf_reduce_kernel(float* __restrict__ out)
{
    __shared__ double sh[BATCH];
    const int i = threadIdx.x;
    sh[i] = (double)g_llh[i];
    __syncthreads();
#pragma unroll
    for (int o = BATCH / 2; o > 0; o >>= 1) {
        if (i < o) sh[i] += sh[i + o];
        __syncthreads();
    }
    if (i == 0) out[0] = (float)sh[0];
}

extern "C" void kernel_launch(void* const* d_in, const int* in_sizes, int n_in,
                              void* d_out, int out_size)
{
    const float* em     = (const float*)d_in[0];
    const void*  tags   = (const void*)d_in[1];
    const int*   mask   = (const int*)d_in[2];
    const float* startT = (const float*)d_in[3];
    const float* endT   = (const float*)d_in[4];
    const float* trans  = (const float*)d_in[5];
    float* out = (float*)d_out;

    crf_forward_kernel<<<BATCH, TPB>>>(em, tags, mask, startT, endT, trans);
    crf_reduce_kernel<<<1, BATCH>>>(out);
}

// round 5
// speedup vs baseline: 1.5447x; 1.5447x over previous
#include <cuda_runtime.h>

#define SEQ   1024
#define BATCH 512
#define NT    64
#define TPB   128   // 2 threads per tag: tid = 2*j + p

// Scratch (device globals; no allocation).
__device__ float g_llh[BATCH];
__device__ int   g_done;

__global__ void __launch_bounds__(TPB)
crf_kernel(const float* __restrict__ em,
           const void* __restrict__ tags_raw,
           const int* __restrict__ mask,
           const float* __restrict__ startT,
           const float* __restrict__ endT,
           const float* __restrict__ trans,
           float* __restrict__ out)
{
    const int b    = blockIdx.x;      // one batch per block
    const int tid  = threadIdx.x;
    const int j    = tid >> 1;        // tag 0..63
    const int p    = tid & 1;         // slice 0/1 (lane bit0 -> shfl xor 1 fold)
    const int lane = tid & 31;
    const int warp = tid >> 5;        // 0..3

    __shared__ float sh_e[2][NT];     // double-buffered beta (linear domain)
    __shared__ float sh_num[4];
    __shared__ int   sh_len[4];
    __shared__ float sh_sum[4];
    __shared__ int   sh_last;

    // ---- tags dtype detection: int64 => every odd 32-bit word is 0 ----
    const int*       t32 = (const int*)tags_raw;
    const long long* t64 = (const long long*)tags_raw;
    bool is64 = true;
#pragma unroll
    for (int k = 0; k < 16; ++k)
        is64 = is64 && (t32[2 * k * 1031 + 1] == 0);

    // ---- exp(transitions): rows [32p, 32p+32) of column j ----
    float eT[32];
#pragma unroll
    for (int i = 0; i < 32; ++i)
        eT[i] = __expf(trans[(32 * p + i) * NT + j]);

    // ---- sequence length (mask monotone) ----
    int cnt = 0;
    for (int t = tid; t < SEQ; t += TPB)
        cnt += mask[t * BATCH + b];
#pragma unroll
    for (int o = 16; o > 0; o >>= 1)
        cnt += __shfl_xor_sync(0xffffffffu, cnt, o);
    if (lane == 0) sh_len[warp] = cnt;
    __syncthreads();
    const int length = sh_len[0] + sh_len[1] + sh_len[2] + sh_len[3];

    // ---- numerator partials: t in [1, length) ----
    float num = 0.f;
    if (is64) {
        for (int t = 1 + tid; t < length; t += TPB) {
            const int pt = (int)t64[(t - 1) * BATCH + b];
            const int ct = (int)t64[t * BATCH + b];
            num += trans[pt * NT + ct] + em[(t * BATCH + b) * NT + ct];
        }
    } else {
        for (int t = 1 + tid; t < length; t += TPB) {
            const int pt = t32[(t - 1) * BATCH + b];
            const int ct = t32[t * BATCH + b];
            num += trans[pt * NT + ct] + em[(t * BATCH + b) * NT + ct];
        }
    }
#pragma unroll
    for (int o = 16; o > 0; o >>= 1)
        num += __shfl_xor_sync(0xffffffffu, num, o);
    if (lane == 0) sh_num[warp] = num;

    // ---- init beta_0 (p==0 owns tag j) + emission prefetch ring ----
    if (p == 0)
        sh_e[0][j] = __expf(startT[j] + em[b * NT + j]);

    float emr[4] = {0.f, 0.f, 0.f, 0.f};
    float expCur = 1.f;
    if (p == 0) {
#pragma unroll
        for (int d = 0; d < 4; ++d)
            emr[d] = (1 + d < length) ? em[((1 + d) * BATCH + b) * NT + j] : 0.f;
        expCur = __expf(emr[0]);
    }

    int ktot = 0;
    __syncthreads();

    for (int t = 1; t < length; ++t) {
        if (p == 0 && t + 4 < length)
            emr[(t + 3) & 3] = em[((t + 4) * BATCH + b) * NT + j];

        const float4* __restrict__ e4 =
            (const float4*)(sh_e[(t - 1) & 1] + 32 * p);
        const float4 a0 = e4[0], a1 = e4[1], a2 = e4[2], a3 = e4[3];
        const float4 a4 = e4[4], a5 = e4[5], a6 = e4[6], a7 = e4[7];

        // renorm every 4 steps (p==0 sees beta[0] as a0.x; exact 2^-k)
        float scale = 1.0f;
        if (p == 0 && (t & 3) == 0) {
            const int k = ((__float_as_int(a0.x) >> 23) & 0xFF) - 127;
            scale = __int_as_float((127 - k) << 23);
            ktot += k;
        }

        // 32-elem partial dot, 8 accumulators (depth 4)
        float s0 = a0.x * eT[0],  s1 = a0.y * eT[1];
        float s2 = a0.z * eT[2],  s3 = a0.w * eT[3];
        float s4 = a1.x * eT[4],  s5 = a1.y * eT[5];
        float s6 = a1.z * eT[6],  s7 = a1.w * eT[7];
        s0 = fmaf(a2.x, eT[8],  s0); s1 = fmaf(a2.y, eT[9],  s1);
        s2 = fmaf(a2.z, eT[10], s2); s3 = fmaf(a2.w, eT[11], s3);
        s4 = fmaf(a3.x, eT[12], s4); s5 = fmaf(a3.y, eT[13], s5);
        s6 = fmaf(a3.z, eT[14], s6); s7 = fmaf(a3.w, eT[15], s7);
        s0 = fmaf(a4.x, eT[16], s0); s1 = fmaf(a4.y, eT[17], s1);
        s2 = fmaf(a4.z, eT[18], s2); s3 = fmaf(a4.w, eT[19], s3);
        s4 = fmaf(a5.x, eT[20], s4); s5 = fmaf(a5.y, eT[21], s5);
        s6 = fmaf(a5.z, eT[22], s6); s7 = fmaf(a5.w, eT[23], s7);
        s0 = fmaf(a6.x, eT[24], s0); s1 = fmaf(a6.y, eT[25], s1);
        s2 = fmaf(a6.z, eT[26], s2); s3 = fmaf(a6.w, eT[27], s3);
        s4 = fmaf(a7.x, eT[28], s4); s5 = fmaf(a7.y, eT[29], s5);
        s6 = fmaf(a7.z, eT[30], s6); s7 = fmaf(a7.w, eT[31], s7);
        float s = ((s0 + s1) + (s2 + s3)) + ((s4 + s5) + (s6 + s7));

        // fold the two slices: partner is lane^1
        s += __shfl_xor_sync(0xffffffffu, s, 1);

        if (p == 0) {
            sh_e[t & 1][j] = s * (expCur * scale);
            expCur = __expf(emr[t & 3]);   // for step t+1 (off critical path)
        }
        __syncthreads();
    }

    // ---- denominator: ktot*ln2 + log(sum_j beta_j * exp(end_j)) ----
    float v = 0.f;
    if (p == 0)
        v = sh_e[(length - 1) & 1][j] * __expf(endT[j]);
#pragma unroll
    for (int o = 16; o > 0; o >>= 1)
        v += __shfl_xor_sync(0xffffffffu, v, o);
    if (lane == 0) sh_sum[warp] = v;
    __syncthreads();

    if (tid == 0) {
        const float sum  = (sh_sum[0] + sh_sum[1]) + (sh_sum[2] + sh_sum[3]);
        const float numt = (sh_num[0] + sh_num[1]) + (sh_num[2] + sh_num[3]);
        const double denom = (double)ktot * 0.6931471805599453
                           + (double)logf(sum);
        const int t0 = is64 ? (int)t64[b] : t32[b];
        const int tl = is64 ? (int)t64[(length - 1) * BATCH + b]
                            : t32[(length - 1) * BATCH + b];
        const double numer = (double)numt
                           + (double)(startT[t0] + em[b * NT + t0] + endT[tl]);
        g_llh[b] = (float)(numer - denom);
    }

    // ---- fused final reduction: last block sums all 512 llh values ----
    __threadfence();
    if (tid == 0)
        sh_last = (atomicAdd(&g_done, 1) == BATCH - 1) ? 1 : 0;
    __syncthreads();

    if (sh_last) {
        __shared__ double red[TPB];
        double acc = 0.0;
#pragma unroll
        for (int k = 0; k < BATCH / TPB; ++k)          // fixed order: 4 each
            acc += (double)g_llh[tid + k * TPB];
        red[tid] = acc;
        __syncthreads();
#pragma unroll
        for (int o = TPB / 2; o > 0; o >>= 1) {
            if (tid < o) red[tid] += red[tid + o];
            __syncthreads();
        }
        if (tid == 0) {
            out[0] = (float)red[0];
            atomicExch(&g_done, 0);    // reset for next graph replay
        }
    }
}

extern "C" void kernel_launch(void* const* d_in, const int* in_sizes, int n_in,
                              void* d_out, int out_size)
{
    const float* em     = (const float*)d_in[0];
    const void*  tags   = (const void*)d_in[1];
    const int*   mask   = (const int*)d_in[2];
    const float* startT = (const float*)d_in[3];
    const float* endT   = (const float*)d_in[4];
    const float* trans  = (const float*)d_in[5];
    float* out = (float*)d_out;

    crf_kernel<<<BATCH, TPB>>>(em, tags, mask, startT, endT, trans, out);
}

// round 6
// speedup vs baseline: 1.6838x; 1.0900x over previous
#include <cuda_runtime.h>

#define SEQ   1024
#define BATCH 512
#define NT    64
#define TPB   64    // thread j = tag j; warp0: tags 0-31, warp1: tags 32-63

// Scratch (device globals; no allocation).
__device__ float g_llh[BATCH];
__device__ int   g_done;

__global__ void __launch_bounds__(TPB)
crf_kernel(const float* __restrict__ em,
           const void* __restrict__ tags_raw,
           const int* __restrict__ mask,
           const float* __restrict__ startT,
           const float* __restrict__ endT,
           const float* __restrict__ trans,
           float* __restrict__ out)
{
    const int b    = blockIdx.x;      // one batch per block
    const int j    = threadIdx.x;     // tag 0..63
    const int lane = j & 31;
    const int warp = j >> 5;          // 0..1

    __shared__ float sh_e[2][NT];     // double-buffered beta (linear domain)
    __shared__ float sh_num[2];
    __shared__ int   sh_len[2];
    __shared__ float sh_sum[2];
    __shared__ int   sh_last;

    // ---- tags dtype detection: int64 => every odd 32-bit word is 0 ----
    const int*       t32 = (const int*)tags_raw;
    const long long* t64 = (const long long*)tags_raw;
    bool is64 = true;
#pragma unroll
    for (int k = 0; k < 16; ++k)
        is64 = is64 && (t32[2 * k * 1031 + 1] == 0);

    // ---- exp(transitions) column j held in registers ----
    float eT[NT];
#pragma unroll
    for (int i = 0; i < NT; ++i)
        eT[i] = __expf(trans[i * NT + j]);

    // ---- sequence length (mask monotone: mask[t] = t < length) ----
    int cnt = 0;
    for (int t = j; t < SEQ; t += TPB)
        cnt += mask[t * BATCH + b];
#pragma unroll
    for (int o = 16; o > 0; o >>= 1)
        cnt += __shfl_xor_sync(0xffffffffu, cnt, o);
    if (lane == 0) sh_len[warp] = cnt;
    __syncthreads();
    const int length = sh_len[0] + sh_len[1];

    // ---- numerator partials: t in [1, length) ----
    float num = 0.f;
    if (is64) {
        for (int t = 1 + j; t < length; t += TPB) {
            const int pt = (int)t64[(t - 1) * BATCH + b];
            const int ct = (int)t64[t * BATCH + b];
            num += trans[pt * NT + ct] + em[(t * BATCH + b) * NT + ct];
        }
    } else {
        for (int t = 1 + j; t < length; t += TPB) {
            const int pt = t32[(t - 1) * BATCH + b];
            const int ct = t32[t * BATCH + b];
            num += trans[pt * NT + ct] + em[(t * BATCH + b) * NT + ct];
        }
    }
#pragma unroll
    for (int o = 16; o > 0; o >>= 1)
        num += __shfl_xor_sync(0xffffffffu, num, o);
    if (lane == 0) sh_num[warp] = num;

    // ---- init beta_0 = exp(start + em_0), linear domain ----
    sh_e[0][j] = __expf(startT[j] + em[b * NT + j]);

    // emission prefetch ring: emr[(s-1)&3] holds raw em for step s
    float emr[4] = {0.f, 0.f, 0.f, 0.f};
#pragma unroll
    for (int d = 0; d < 4; ++d)
        emr[d] = (1 + d < length) ? em[((1 + d) * BATCH + b) * NT + j] : 0.f;
    float expCur = __expf(emr[0]);    // exp(em) for step t=1

    int ktot = 0;                     // power-of-2 renorm exponent (uniform)
    __syncthreads();

    for (int t = 1; t < length; ++t) {
        if (t + 4 < length)
            emr[(t + 3) & 3] = em[((t + 4) * BATCH + b) * NT + j];

        const float4* __restrict__ e4 = (const float4*)sh_e[(t - 1) & 1];
        const float4 a0 = e4[0];

        // renorm every 4 steps: exact power-of-2 scale from beta[0] (= a0.x)
        float scale = 1.0f;
        if ((t & 3) == 0) {
            const int k = ((__float_as_int(a0.x) >> 23) & 0xFF) - 127;
            scale = __int_as_float((127 - k) << 23);   // 2^-k, exact
            ktot += k;
        }

        // full 64-elem dot for tag j: 16 float4 broadcasts, 8 accumulators
        float s0 = a0.x * eT[0], s1 = a0.y * eT[1];
        float s2 = a0.z * eT[2], s3 = a0.w * eT[3];
        float s4 = 0.f, s5 = 0.f, s6 = 0.f, s7 = 0.f;
#pragma unroll
        for (int k = 1; k < 16; ++k) {
            const float4 a = e4[k];
            if (k & 1) {
                s4 = fmaf(a.x, eT[4 * k + 0], s4);
                s5 = fmaf(a.y, eT[4 * k + 1], s5);
                s6 = fmaf(a.z, eT[4 * k + 2], s6);
                s7 = fmaf(a.w, eT[4 * k + 3], s7);
            } else {
                s0 = fmaf(a.x, eT[4 * k + 0], s0);
                s1 = fmaf(a.y, eT[4 * k + 1], s1);
                s2 = fmaf(a.z, eT[4 * k + 2], s2);
                s3 = fmaf(a.w, eT[4 * k + 3], s3);
            }
        }
        const float s = ((s0 + s1) + (s2 + s3)) + ((s4 + s5) + (s6 + s7));

        sh_e[t & 1][j] = s * (expCur * scale);
        expCur = __expf(emr[t & 3]);  // for step t+1 (off critical path)
        __syncthreads();
    }

    // ---- denominator: ktot*ln2 + log(sum_j beta_j * exp(end_j)) ----
    float v = sh_e[(length - 1) & 1][j] * __expf(endT[j]);
#pragma unroll
    for (int o = 16; o > 0; o >>= 1)
        v += __shfl_xor_sync(0xffffffffu, v, o);
    if (lane == 0) sh_sum[warp] = v;
    __syncthreads();

    if (j == 0) {
        const double denom = (double)ktot * 0.6931471805599453
                           + (double)logf(sh_sum[0] + sh_sum[1]);
        const int t0 = is64 ? (int)t64[b] : t32[b];
        const int tl = is64 ? (int)t64[(length - 1) * BATCH + b]
                            : t32[(length - 1) * BATCH + b];
        const double numer = (double)(sh_num[0] + sh_num[1])
                           + (double)(startT[t0] + em[b * NT + t0] + endT[tl]);
        g_llh[b] = (float)(numer - denom);
    }

    // ---- fused final reduction: last block sums all 512 llh values ----
    __threadfence();
    if (j == 0)
        sh_last = (atomicAdd(&g_done, 1) == BATCH - 1) ? 1 : 0;
    __syncthreads();

    if (sh_last) {
        __shared__ double red[TPB];
        double acc = 0.0;
#pragma unroll
        for (int k = 0; k < BATCH / TPB; ++k)          // fixed order: 8 each
            acc += (double)g_llh[j + k * TPB];
        red[j] = acc;
        __syncthreads();
#pragma unroll
        for (int o = TPB / 2; o > 0; o >>= 1) {
            if (j < o) red[j] += red[j + o];
            __syncthreads();
        }
        if (j == 0) {
            out[0] = (float)red[0];
            atomicExch(&g_done, 0);    // reset for next graph replay
        }
    }
}

extern "C" void kernel_launch(void* const* d_in, const int* in_sizes, int n_in,
                              void* d_out, int out_size)
{
    const float* em     = (const float*)d_in[0];
    const void*  tags   = (const void*)d_in[1];
    const int*   mask   = (const int*)d_in[2];
    const float* startT = (const float*)d_in[3];
    const float* endT   = (const float*)d_in[4];
    const float* trans  = (const float*)d_in[5];
    float* out = (float*)d_out;

    crf_kernel<<<BATCH, TPB>>>(em, tags, mask, startT, endT, trans, out);
}

// round 8
// speedup vs baseline: 1.7045x; 1.0123x over previous
#include <cuda_runtime.h>

#define SEQ   1024
#define BATCH 512
#define NT    64
#define TPB   64    // thread j = tag j; warp0: tags 0-31, warp1: tags 32-63

// Scratch (device globals; no allocation).
__device__ float g_llh[BATCH];
__device__ int   g_done;

typedef unsigned long long u64;

__device__ __forceinline__ u64 fma2(u64 a, u64 b, u64 c) {
    u64 d;
    asm("fma.rn.f32x2 %0, %1, %2, %3;" : "=l"(d) : "l"(a), "l"(b), "l"(c));
    return d;
}
__device__ __forceinline__ u64 add2(u64 a, u64 b) {
    u64 d;
    asm("add.rn.f32x2 %0, %1, %2;" : "=l"(d) : "l"(a), "l"(b));
    return d;
}
__device__ __forceinline__ u64 pack2(float lo, float hi) {
    u64 r;
    asm("mov.b64 %0, {%1,%2};" : "=l"(r) : "f"(lo), "f"(hi));
    return r;
}
__device__ __forceinline__ float unpack_sum(u64 v) {
    float lo, hi;
    asm("mov.b64 {%0,%1}, %2;" : "=f"(lo), "=f"(hi) : "l"(v));
    return lo + hi;
}

__global__ void __launch_bounds__(TPB)
crf_kernel(const float* __restrict__ em,
           const void* __restrict__ tags_raw,
           const int* __restrict__ mask,
           const float* __restrict__ startT,
           const float* __restrict__ endT,
           const float* __restrict__ trans,
           float* __restrict__ out)
{
    const int b    = blockIdx.x;      // one batch per block
    const int j    = threadIdx.x;     // tag 0..63
    const int lane = j & 31;
    const int warp = j >> 5;          // 0..1

    __shared__ __align__(16) float sh_e[2][NT];  // double-buffered beta
    __shared__ float sh_num[2];
    __shared__ int   sh_len[2];
    __shared__ float sh_sum[2];
    __shared__ int   sh_last;

    // ---- tags dtype detection: int64 => every odd 32-bit word is 0 ----
    const int*       t32 = (const int*)tags_raw;
    const long long* t64 = (const long long*)tags_raw;
    bool is64 = true;
#pragma unroll
    for (int k = 0; k < 16; ++k)
        is64 = is64 && (t32[2 * k * 1031 + 1] == 0);

    // ---- exp(transitions) column j as 32 packed f32x2 pairs over i ----
    u64 eT2[NT / 2];
#pragma unroll
    for (int k = 0; k < NT / 2; ++k)
        eT2[k] = pack2(__expf(trans[(2 * k + 0) * NT + j]),
                       __expf(trans[(2 * k + 1) * NT + j]));

    // ---- sequence length (mask monotone: mask[t] = t < length) ----
    int cnt = 0;
    for (int t = j; t < SEQ; t += TPB)
        cnt += mask[t * BATCH + b];
#pragma unroll
    for (int o = 16; o > 0; o >>= 1)
        cnt += __shfl_xor_sync(0xffffffffu, cnt, o);
    if (lane == 0) sh_len[warp] = cnt;
    __syncthreads();
    const int length = sh_len[0] + sh_len[1];

    // ---- numerator partials: t in [1, length) ----
    float num = 0.f;
    if (is64) {
        for (int t = 1 + j; t < length; t += TPB) {
            const int pt = (int)t64[(t - 1) * BATCH + b];
            const int ct = (int)t64[t * BATCH + b];
            num += trans[pt * NT + ct] + em[(t * BATCH + b) * NT + ct];
        }
    } else {
        for (int t = 1 + j; t < length; t += TPB) {
            const int pt = t32[(t - 1) * BATCH + b];
            const int ct = t32[t * BATCH + b];
            num += trans[pt * NT + ct] + em[(t * BATCH + b) * NT + ct];
        }
    }
#pragma unroll
    for (int o = 16; o > 0; o >>= 1)
        num += __shfl_xor_sync(0xffffffffu, num, o);
    if (lane == 0) sh_num[warp] = num;

    // ---- init beta_0 = exp(start + em_0), linear domain ----
    sh_e[0][j] = __expf(startT[j] + em[b * NT + j]);

    // emission prefetch ring: emr[(s-1)&3] holds raw em for step s
    float emr[4] = {0.f, 0.f, 0.f, 0.f};
#pragma unroll
    for (int d = 0; d < 4; ++d)
        emr[d] = (1 + d < length) ? em[((1 + d) * BATCH + b) * NT + j] : 0.f;
    float expCur = __expf(emr[0]);    // exp(em) for step t=1

    int ktot = 0;                     // power-of-2 renorm exponent (uniform)
    __syncthreads();

    for (int t = 1; t < length; ++t) {
        if (t + 4 < length)
            emr[(t + 3) & 3] = em[((t + 4) * BATCH + b) * NT + j];

        const float* __restrict__ e = sh_e[(t - 1) & 1];
        const ulonglong2* __restrict__ e2 = (const ulonglong2*)e;

        // renorm every 4 steps: exact power-of-2 scale from beta[0]
        float scale = 1.0f;
        if ((t & 3) == 0) {
            const int k = ((__float_as_int(e[0]) >> 23) & 0xFF) - 127;
            scale = __int_as_float((127 - k) << 23);   // 2^-k, exact
            ktot += k;
        }

        // FULL 64-elem dot as 32 packed FFMA2 (16 ulonglong2 = 64 floats)
        u64 a0 = 0ull, a1 = 0ull, a2 = 0ull, a3 = 0ull;
#pragma unroll
        for (int k = 0; k < 16; ++k) {         // 16 LDS.128, 2 FFMA2 each
            const ulonglong2 q = e2[k];        // sources floats 4k..4k+3
            if (k & 1) {
                a2 = fma2(q.x, eT2[2 * k + 0], a2);
                a3 = fma2(q.y, eT2[2 * k + 1], a3);
            } else {
                a0 = fma2(q.x, eT2[2 * k + 0], a0);
                a1 = fma2(q.y, eT2[2 * k + 1], a1);
            }
        }
        const float s = unpack_sum(add2(add2(a0, a1), add2(a2, a3)));

        sh_e[t & 1][j] = s * (expCur * scale);
        expCur = __expf(emr[t & 3]);  // for step t+1 (off critical path)
        __syncthreads();
    }

    // ---- denominator: ktot*ln2 + log(sum_j beta_j * exp(end_j)) ----
    float v = sh_e[(length - 1) & 1][j] * __expf(endT[j]);
#pragma unroll
    for (int o = 16; o > 0; o >>= 1)
        v += __shfl_xor_sync(0xffffffffu, v, o);
    if (lane == 0) sh_sum[warp] = v;
    __syncthreads();

    if (j == 0) {
        const double denom = (double)ktot * 0.6931471805599453
                           + (double)logf(sh_sum[0] + sh_sum[1]);
        const int t0 = is64 ? (int)t64[b] : t32[b];
        const int tl = is64 ? (int)t64[(length - 1) * BATCH + b]
                            : t32[(length - 1) * BATCH + b];
        const double numer = (double)(sh_num[0] + sh_num[1])
                           + (double)(startT[t0] + em[b * NT + t0] + endT[tl]);
        g_llh[b] = (float)(numer - denom);
    }

    // ---- fused final reduction: last block sums all 512 llh values ----
    __threadfence();
    if (j == 0)
        sh_last = (atomicAdd(&g_done, 1) == BATCH - 1) ? 1 : 0;
    __syncthreads();

    if (sh_last) {
        __shared__ double red[TPB];
        double acc = 0.0;
#pragma unroll
        for (int k = 0; k < BATCH / TPB; ++k)          // fixed order: 8 each
            acc += (double)g_llh[j + k * TPB];
        red[j] = acc;
        __syncthreads();
#pragma unroll
        for (int o = TPB / 2; o > 0; o >>= 1) {
            if (j < o) red[j] += red[j + o];
            __syncthreads();
        }
        if (j == 0) {
            out[0] = (float)red[0];
            atomicExch(&g_done, 0);    // reset for next graph replay
        }
    }
}

extern "C" void kernel_launch(void* const* d_in, const int* in_sizes, int n_in,
                              void* d_out, int out_size)
{
    const float* em     = (const float*)d_in[0];
    const void*  tags   = (const void*)d_in[1];
    const int*   mask   = (const int*)d_in[2];
    const float* startT = (const float*)d_in[3];
    const float* endT   = (const float*)d_in[4];
    const float* trans  = (const float*)d_in[5];
    float* out = (float*)d_out;

    crf_kernel<<<BATCH, TPB>>>(em, tags, mask, startT, endT, trans, out);
}

// round 9
// speedup vs baseline: 3.2296x; 1.8947x over previous
#include <cuda_runtime.h>

#define SEQ   1024
#define BATCH 512
#define NT    64
#define TPB   64    // thread j = tag j; warp0: tags 0-31, warp1: tags 32-63

// Scratch (device globals; no allocation).
__device__ float g_llh[BATCH];
__device__ int   g_done;

typedef unsigned long long u64;

__device__ __forceinline__ u64 fma2(u64 a, u64 b, u64 c) {
    u64 d;
    asm("fma.rn.f32x2 %0, %1, %2, %3;" : "=l"(d) : "l"(a), "l"(b), "l"(c));
    return d;
}
__device__ __forceinline__ u64 add2(u64 a, u64 b) {
    u64 d;
    asm("add.rn.f32x2 %0, %1, %2;" : "=l"(d) : "l"(a), "l"(b));
    return d;
}
__device__ __forceinline__ u64 pack2(float lo, float hi) {
    u64 r;
    asm("mov.b64 %0, {%1,%2};" : "=l"(r) : "f"(lo), "f"(hi));
    return r;
}
__device__ __forceinline__ float unpack_sum(u64 v) {
    float lo, hi;
    asm("mov.b64 {%0,%1}, %2;" : "=f"(lo), "=f"(hi) : "l"(v));
    return lo + hi;
}

__global__ void __launch_bounds__(TPB)
crf_kernel(const float* __restrict__ em,
           const void* __restrict__ tags_raw,
           const int* __restrict__ mask,
           const float* __restrict__ startT,
           const float* __restrict__ endT,
           const float* __restrict__ trans,
           float* __restrict__ out)
{
    const int b    = blockIdx.x;      // one batch per block
    const int j    = threadIdx.x;     // tag 0..63
    const int lane = j & 31;
    const int warp = j >> 5;          // 0..1

    __shared__ __align__(16) float sh_e[2][NT];  // double-buffered beta
    __shared__ float sh_num[2];
    __shared__ int   sh_len[2];
    __shared__ float sh_sum[2];
    __shared__ int   sh_last;

    // ---- tags dtype detection: int64 => every odd 32-bit word is 0 ----
    const int*       t32 = (const int*)tags_raw;
    const long long* t64 = (const long long*)tags_raw;
    bool is64 = true;
#pragma unroll
    for (int k = 0; k < 16; ++k)
        is64 = is64 && (t32[2 * k * 1031 + 1] == 0);

    // ---- exp(transitions) column j as 32 packed f32x2 pairs over i ----
    u64 eT2[NT / 2];
#pragma unroll
    for (int k = 0; k < NT / 2; ++k)
        eT2[k] = pack2(__expf(trans[(2 * k + 0) * NT + j]),
                       __expf(trans[(2 * k + 1) * NT + j]));

    // ---- sequence length (mask monotone: mask[t] = t < length) ----
    int cnt = 0;
    for (int t = j; t < SEQ; t += TPB)
        cnt += mask[t * BATCH + b];
#pragma unroll
    for (int o = 16; o > 0; o >>= 1)
        cnt += __shfl_xor_sync(0xffffffffu, cnt, o);
    if (lane == 0) sh_len[warp] = cnt;
    __syncthreads();
    const int length = sh_len[0] + sh_len[1];

    // ---- numerator partials: t in [1, length) ----
    float num = 0.f;
    if (is64) {
        for (int t = 1 + j; t < length; t += TPB) {
            const int pt = (int)t64[(t - 1) * BATCH + b];
            const int ct = (int)t64[t * BATCH + b];
            num += trans[pt * NT + ct] + em[(t * BATCH + b) * NT + ct];
        }
    } else {
        for (int t = 1 + j; t < length; t += TPB) {
            const int pt = t32[(t - 1) * BATCH + b];
            const int ct = t32[t * BATCH + b];
            num += trans[pt * NT + ct] + em[(t * BATCH + b) * NT + ct];
        }
    }
#pragma unroll
    for (int o = 16; o > 0; o >>= 1)
        num += __shfl_xor_sync(0xffffffffu, num, o);
    if (lane == 0) sh_num[warp] = num;

    // ---- init beta_0 = exp(start + em_0), linear domain ----
    sh_e[0][j] = __expf(startT[j] + em[b * NT + j]);

#define IDX(T) (((T) * BATCH + b) * NT + j)

    // register prefetch: p0..p3 = raw em for steps t..t+3 (t group base)
    float p0 = (1 < length) ? em[IDX(1)] : 0.f;
    float p1 = (2 < length) ? em[IDX(2)] : 0.f;
    float p2 = (3 < length) ? em[IDX(3)] : 0.f;
    float p3 = (4 < length) ? em[IDX(4)] : 0.f;

    int ktot = 0;                     // power-of-2 renorm exponent (uniform)
    __syncthreads();

    // STEP: prev-buffer parity PP is compile-time; RENORM folds exact 2^-k.
#define STEP(PP, EXV, RENORM) do {                                         \
        const float* __restrict__ e = sh_e[PP];                             \
        const ulonglong2* __restrict__ e2 = (const ulonglong2*)e;           \
        float scale_ = 1.0f;                                                \
        if (RENORM) {                                                       \
            const int kk = ((__float_as_int(e[0]) >> 23) & 0xFF) - 127;     \
            scale_ = __int_as_float((127 - kk) << 23);                      \
            ktot += kk;                                                     \
        }                                                                   \
        u64 a0 = 0ull, a1 = 0ull, a2 = 0ull, a3 = 0ull;                     \
        _Pragma("unroll")                                                   \
        for (int k = 0; k < 16; ++k) {                                      \
            const ulonglong2 q = e2[k];                                     \
            if (k & 1) { a2 = fma2(q.x, eT2[2*k],   a2);                    \
                         a3 = fma2(q.y, eT2[2*k+1], a3); }                  \
            else       { a0 = fma2(q.x, eT2[2*k],   a0);                    \
                         a1 = fma2(q.y, eT2[2*k+1], a1); }                  \
        }                                                                   \
        const float s_ = unpack_sum(add2(add2(a0, a1), add2(a2, a3)));      \
        sh_e[(PP) ^ 1][j] = s_ * ((EXV) * scale_);                          \
        __syncthreads();                                                    \
    } while (0)

    int t = 1;   // group base; always odd => parities compile-time
    for (; t + 3 < length; t += 4) {
        // prefetch next group's raw emissions (registers, MLP=4)
        const float n0 = (t + 4 < length) ? em[IDX(t + 4)] : 0.f;
        const float n1 = (t + 5 < length) ? em[IDX(t + 5)] : 0.f;
        const float n2 = (t + 6 < length) ? em[IDX(t + 6)] : 0.f;
        const float n3 = (t + 7 < length) ? em[IDX(t + 7)] : 0.f;

        // exps for this group's 4 steps (inputs arrived a group ago)
        const float ex0 = __expf(p0);
        const float ex1 = __expf(p1);
        const float ex2 = __expf(p2);
        const float ex3 = __expf(p3);

        STEP(0, ex0, true);    // step t   (renorm once per group; exact)
        STEP(1, ex1, false);   // step t+1
        STEP(0, ex2, false);   // step t+2
        STEP(1, ex3, false);   // step t+3

        p0 = n0; p1 = n1; p2 = n2; p3 = n3;
    }

    // tail: up to 3 steps, statically unrolled (t is odd here)
    if (t     < length) STEP(0, __expf(p0), false);
    if (t + 1 < length) STEP(1, __expf(p1), false);
    if (t + 2 < length) STEP(0, __expf(p2), false);

#undef STEP
#undef IDX

    // ---- denominator: ktot*ln2 + log(sum_j beta_j * exp(end_j)) ----
    float v = sh_e[(length - 1) & 1][j] * __expf(endT[j]);
#pragma unroll
    for (int o = 16; o > 0; o >>= 1)
        v += __shfl_xor_sync(0xffffffffu, v, o);
    if (lane == 0) sh_sum[warp] = v;
    __syncthreads();

    if (j == 0) {
        const double denom = (double)ktot * 0.6931471805599453
                           + (double)logf(sh_sum[0] + sh_sum[1]);
        const int t0 = is64 ? (int)t64[b] : t32[b];
        const int tl = is64 ? (int)t64[(length - 1) * BATCH + b]
                            : t32[(length - 1) * BATCH + b];
        const double numer = (double)(sh_num[0] + sh_num[1])
                           + (double)(startT[t0] + em[b * NT + t0] + endT[tl]);
        g_llh[b] = (float)(numer - denom);
    }

    // ---- fused final reduction: last block sums all 512 llh values ----
    __threadfence();
    if (j == 0)
        sh_last = (atomicAdd(&g_done, 1) == BATCH - 1) ? 1 : 0;
    __syncthreads();

    if (sh_last) {
        __shared__ double red[TPB];
        double acc = 0.0;
#pragma unroll
        for (int k = 0; k < BATCH / TPB; ++k)          // fixed order: 8 each
            acc += (double)g_llh[j + k * TPB];
        red[j] = acc;
        __syncthreads();
#pragma unroll
        for (int o = TPB / 2; o > 0; o >>= 1) {
            if (j < o) red[j] += red[j + o];
            __syncthreads();
        }
        if (j == 0) {
            out[0] = (float)red[0];
            atomicExch(&g_done, 0);    // reset for next graph replay
        }
    }
}

extern "C" void kernel_launch(void* const* d_in, const int* in_sizes, int n_in,
                              void* d_out, int out_size)
{
    const float* em     = (const float*)d_in[0];
    const void*  tags   = (const void*)d_in[1];
    const int*   mask   = (const int*)d_in[2];
    const float* startT = (const float*)d_in[3];
    const float* endT   = (const float*)d_in[4];
    const float* trans  = (const float*)d_in[5];
    float* out = (float*)d_out;

    crf_kernel<<<BATCH, TPB>>>(em, tags, mask, startT, endT, trans, out);
}

// round 10
// speedup vs baseline: 3.6526x; 1.1310x over previous
#include <cuda_runtime.h>

#define SEQ   1024
#define BATCH 512
#define NT    64
#define TPB   64    // thread j = tag j; 2 warps per block

// Scratch (device globals; no allocation).
__device__ float g_vec[2][BATCH][NT];  // [0]=forward F~, [1]=backward u
__device__ int   g_kt[2][BATCH];
__device__ float g_num[BATCH];
__device__ int   g_pair[BATCH];
__device__ float g_llh[BATCH];
__device__ int   g_done;

typedef unsigned long long u64;

__device__ __forceinline__ u64 fma2(u64 a, u64 b, u64 c) {
    u64 d;
    asm("fma.rn.f32x2 %0, %1, %2, %3;" : "=l"(d) : "l"(a), "l"(b), "l"(c));
    return d;
}
__device__ __forceinline__ u64 add2(u64 a, u64 b) {
    u64 d;
    asm("add.rn.f32x2 %0, %1, %2;" : "=l"(d) : "l"(a), "l"(b));
    return d;
}
__device__ __forceinline__ u64 pack2(float lo, float hi) {
    u64 r;
    asm("mov.b64 %0, {%1,%2};" : "=l"(r) : "f"(lo), "f"(hi));
    return r;
}
__device__ __forceinline__ float unpack_sum(u64 v) {
    float lo, hi;
    asm("mov.b64 {%0,%1}, %2;" : "=f"(lo), "=f"(hi) : "l"(v));
    return lo + hi;
}

__global__ void __launch_bounds__(TPB)
crf_kernel(const float* __restrict__ em,
           const void* __restrict__ tags_raw,
           const int* __restrict__ mask,
           const float* __restrict__ startT,
           const float* __restrict__ endT,
           const float* __restrict__ trans,
           float* __restrict__ out)
{
    const int bb   = blockIdx.x;
    const int b    = bb >> 1;         // batch
    const int half = bb & 1;          // 0 = forward, 1 = backward
    const int j    = threadIdx.x;     // tag 0..63
    const int lane = j & 31;
    const int warp = j >> 5;

    __shared__ __align__(16) float sh_e[2][NT];
    __shared__ float sh_red[2];
    __shared__ int   sh_len[2];
    __shared__ int   sh_go, sh_last;

    // ---- exp(transitions): forward = column j, backward = row j ----
    u64 eT2[NT / 2];
    if (half == 0) {
#pragma unroll
        for (int k = 0; k < NT / 2; ++k)
            eT2[k] = pack2(__expf(trans[(2 * k + 0) * NT + j]),
                           __expf(trans[(2 * k + 1) * NT + j]));
    } else {
#pragma unroll
        for (int k = 0; k < NT / 2; ++k)
            eT2[k] = pack2(__expf(trans[j * NT + 2 * k + 0]),
                           __expf(trans[j * NT + 2 * k + 1]));
    }

    // ---- sequence length (mask monotone: mask[t] = t < length) ----
    int cnt = 0;
    for (int t = j; t < SEQ; t += TPB)
        cnt += mask[t * BATCH + b];
#pragma unroll
    for (int o = 16; o > 0; o >>= 1)
        cnt += __shfl_xor_sync(0xffffffffu, cnt, o);
    if (lane == 0) sh_len[warp] = cnt;
    __syncthreads();
    const int length = sh_len[0] + sh_len[1];

    const int m = (length - 1) >> 1;          // meeting point
    const int n = half ? (length - 1 - m) : m; // my step count

    // ---- numerator (forward block only) ----
    if (half == 0) {
        const int*       t32 = (const int*)tags_raw;
        const long long* t64 = (const long long*)tags_raw;
        bool is64 = true;
#pragma unroll
        for (int k = 0; k < 16; ++k)
            is64 = is64 && (t32[2 * k * 1031 + 1] == 0);

        float num = 0.f;
        if (is64) {
            for (int t = 1 + j; t < length; t += TPB) {
                const int pt = (int)t64[(t - 1) * BATCH + b];
                const int ct = (int)t64[t * BATCH + b];
                num += trans[pt * NT + ct] + em[(t * BATCH + b) * NT + ct];
            }
        } else {
            for (int t = 1 + j; t < length; t += TPB) {
                const int pt = t32[(t - 1) * BATCH + b];
                const int ct = t32[t * BATCH + b];
                num += trans[pt * NT + ct] + em[(t * BATCH + b) * NT + ct];
            }
        }
#pragma unroll
        for (int o = 16; o > 0; o >>= 1)
            num += __shfl_xor_sync(0xffffffffu, num, o);
        if (lane == 0) sh_red[warp] = num;
        __syncthreads();
        if (j == 0) {
            const int t0 = is64 ? (int)t64[b] : t32[b];
            const int tl = is64 ? (int)t64[(length - 1) * BATCH + b]
                                : t32[(length - 1) * BATCH + b];
            g_num[b] = sh_red[0] + sh_red[1]
                     + startT[t0] + em[b * NT + t0] + endT[tl];
        }
        __syncthreads();
    }

    // ---- init vector + em index mapping ----
    // forward: steps v=1..n use em[v];       init = exp(start + em_0)
    // backward: steps v=1..n use em[L-1-v];  init = exp(end + em_{L-1})
    const int base   = half ? (((length - 1) * BATCH + b) * NT + j)
                            : (b * NT + j);
    const int stride = half ? -(BATCH * NT) : (BATCH * NT);
    sh_e[0][j] = half ? __expf(endT[j] + em[base])
                      : __expf(startT[j] + em[base]);

    // register prefetch: p0..p3 = raw em for steps v..v+3
    float p0 = (1 <= n) ? em[base + 1 * stride] : 0.f;
    float p1 = (2 <= n) ? em[base + 2 * stride] : 0.f;
    float p2 = (3 <= n) ? em[base + 3 * stride] : 0.f;
    float p3 = (4 <= n) ? em[base + 4 * stride] : 0.f;

    int ktot = 0;
    __syncthreads();

#define STEP(PP, EXV, RENORM) do {                                         \
        const float* __restrict__ e = sh_e[PP];                             \
        const ulonglong2* __restrict__ e2 = (const ulonglong2*)e;           \
        float scale_ = 1.0f;                                                \
        if (RENORM) {                                                       \
            const int kk = ((__float_as_int(e[0]) >> 23) & 0xFF) - 127;     \
            scale_ = __int_as_float((127 - kk) << 23);                      \
            ktot += kk;                                                     \
        }                                                                   \
        u64 a0 = 0ull, a1 = 0ull, a2 = 0ull, a3 = 0ull;                     \
        _Pragma("unroll")                                                   \
        for (int k = 0; k < 16; ++k) {                                      \
            const ulonglong2 q = e2[k];                                     \
            if (k & 1) { a2 = fma2(q.x, eT2[2*k],   a2);                    \
                         a3 = fma2(q.y, eT2[2*k+1], a3); }                  \
            else       { a0 = fma2(q.x, eT2[2*k],   a0);                    \
                         a1 = fma2(q.y, eT2[2*k+1], a1); }                  \
        }                                                                   \
        const float s_ = unpack_sum(add2(add2(a0, a1), add2(a2, a3)));      \
        sh_e[(PP) ^ 1][j] = s_ * ((EXV) * scale_);                          \
        __syncthreads();                                                    \
    } while (0)

    int v = 1;   // step counter; group base odd => compile-time parities
    for (; v + 3 <= n; v += 4) {
        const float n0 = (v + 4 <= n) ? em[base + (v + 4) * stride] : 0.f;
        const float n1 = (v + 5 <= n) ? em[base + (v + 5) * stride] : 0.f;
        const float n2 = (v + 6 <= n) ? em[base + (v + 6) * stride] : 0.f;
        const float n3 = (v + 7 <= n) ? em[base + (v + 7) * stride] : 0.f;

        const float ex0 = __expf(p0);
        const float ex1 = __expf(p1);
        const float ex2 = __expf(p2);
        const float ex3 = __expf(p3);

        STEP(0, ex0, true);
        STEP(1, ex1, false);
        STEP(0, ex2, false);
        STEP(1, ex3, false);

        p0 = n0; p1 = n1; p2 = n2; p3 = n3;
    }
    if (v     <= n) STEP(0, __expf(p0), false);
    if (v + 1 <= n) STEP(1, __expf(p1), false);
    if (v + 2 <= n) STEP(0, __expf(p2), false);
#undef STEP

    // ---- publish my half ----
    g_vec[half][b][j] = sh_e[n & 1][j];
    if (j == 0) g_kt[half][b] = ktot;

    __threadfence();
    if (j == 0)
        sh_go = (atomicAdd(&g_pair[b], 1) == 1) ? 1 : 0;
    __syncthreads();

    if (sh_go) {
        __threadfence();   // acquire side
        // Z = sum_j F_m(j) * u_m(j) * exp(-em_m(j))   (em_m counted twice)
        const float Ff  = g_vec[0][b][j];
        const float Ub  = g_vec[1][b][j];
        const float emm = em[(m * BATCH + b) * NT + j];
        float s = Ff * Ub * __expf(-emm);
#pragma unroll
        for (int o = 16; o > 0; o >>= 1)
            s += __shfl_xor_sync(0xffffffffu, s, o);
        if (lane == 0) sh_red[warp] = s;
        __syncthreads();

        if (j == 0) {
            const int kt = g_kt[0][b] + g_kt[1][b];
            const double denom = (double)kt * 0.6931471805599453
                               + (double)logf(sh_red[0] + sh_red[1]);
            g_llh[b] = (float)((double)g_num[b] - denom);
            g_pair[b] = 0;                 // reset for next replay
        }

        // ---- final reduction by the last combiner ----
        __threadfence();
        if (j == 0)
            sh_last = (atomicAdd(&g_done, 1) == BATCH - 1) ? 1 : 0;
        __syncthreads();

        if (sh_last) {
            __shared__ double red[TPB];
            double acc = 0.0;
#pragma unroll
            for (int k = 0; k < BATCH / TPB; ++k)      // fixed order
                acc += (double)g_llh[j + k * TPB];
            red[j] = acc;
            __syncthreads();
#pragma unroll
            for (int o = TPB / 2; o > 0; o >>= 1) {
                if (j < o) red[j] += red[j + o];
                __syncthreads();
            }
            if (j == 0) {
                out[0] = (float)red[0];
                atomicExch(&g_done, 0);    // reset for next replay
            }
        }
    }
}

extern "C" void kernel_launch(void* const* d_in, const int* in_sizes, int n_in,
                              void* d_out, int out_size)
{
    const float* em     = (const float*)d_in[0];
    const void*  tags   = (const void*)d_in[1];
    const int*   mask   = (const int*)d_in[2];
    const float* startT = (const float*)d_in[3];
    const float* endT   = (const float*)d_in[4];
    const float* trans  = (const float*)d_in[5];
    float* out = (float*)d_out;

    crf_kernel<<<2 * BATCH, TPB>>>(em, tags, mask, startT, endT, trans, out);
}